// round 3
// baseline (speedup 1.0000x reference)
#include <cuda_runtime.h>

#define BATCH 32
#define SEQ   768
#define CDIM  256
#define HDIM  64
#define ROWS  (BATCH * SEQ)      // 24576
#define QTILES (SEQ / 64)        // 12

typedef unsigned long long u64;

// Scratch for projected Q, K, V (no cudaMalloc allowed)
__device__ float g_q[ROWS * HDIM];
__device__ float g_k[ROWS * HDIM];
__device__ float g_v[ROWS * HDIM];

// ---------------------------------------------------------------------------
// packed fp32x2 helpers (sm_100+ PTX)
// ---------------------------------------------------------------------------
__device__ __forceinline__ u64 pack2(float lo, float hi) {
    u64 r; asm("mov.b64 %0, {%1,%2};" : "=l"(r) : "f"(lo), "f"(hi)); return r;
}
__device__ __forceinline__ void unpack2(u64 v, float& lo, float& hi) {
    asm("mov.b64 {%0,%1}, %2;" : "=f"(lo), "=f"(hi) : "l"(v));
}
__device__ __forceinline__ u64 fma2(u64 a, u64 b, u64 c) {
    u64 d; asm("fma.rn.f32x2 %0, %1, %2, %3;" : "=l"(d) : "l"(a), "l"(b), "l"(c)); return d;
}
__device__ __forceinline__ u64 mul2(u64 a, u64 b) {
    u64 d; asm("mul.rn.f32x2 %0, %1, %2;" : "=l"(d) : "l"(a), "l"(b)); return d;
}

#define DUP_STRIDE 140   // floats; duplicated ("(v,v)") operand buffers
#define B_STRIDE   68    // floats; normal b-operand buffers

// ---------------------------------------------------------------------------
// Kernel 1: fused QKV projection on f32x2.
// Grid: ROWS/64 = 384 CTAs, 256 threads. Each CTA: 64 rows x (3 x 64) outputs.
// smem: xs_dup[64][140] (x^T, duplicated) + ws[3*64][68] = 88064 B.
// ---------------------------------------------------------------------------
__global__ __launch_bounds__(256, 2) void qkv_kernel(
    const float* __restrict__ x,
    const float* __restrict__ wq,
    const float* __restrict__ wk,
    const float* __restrict__ wv)
{
    extern __shared__ float sm[];
    float (*xs)[DUP_STRIDE] = (float(*)[DUP_STRIDE])sm;               // xs[c][2r(+1)] = x[r][c] dup
    float (*ws)[B_STRIDE]   = (float(*)[B_STRIDE])(sm + 64 * DUP_STRIDE); // ws[w*64+k][h]

    const int r0 = blockIdx.x * 64;
    const int t  = threadIdx.x;
    const int tr = t >> 4;     // 0..15
    const int tc = t & 15;     // 0..15

    u64 acc[3][4][2];
    #pragma unroll
    for (int w = 0; w < 3; w++)
        #pragma unroll
        for (int i = 0; i < 4; i++)
            #pragma unroll
            for (int j = 0; j < 2; j++) acc[w][i][j] = 0ull;

    // prefetch x chunk 0 into registers
    float4 xr[4];
    #pragma unroll
    for (int rep = 0; rep < 4; rep++) {
        int idx = t + rep * 256;
        int r = idx >> 4, c4 = (idx & 15) * 4;
        xr[rep] = *(const float4*)&x[(size_t)(r0 + r) * CDIM + c4];
    }

    for (int ch = 0; ch < 4; ch++) {
        __syncthreads();   // previous chunk's compute done with smem
        // store prefetched x chunk, duplicated+transposed
        #pragma unroll
        for (int rep = 0; rep < 4; rep++) {
            int idx = t + rep * 256;
            int r = idx >> 4, c4 = (idx & 15) * 4;
            float v[4] = {xr[rep].x, xr[rep].y, xr[rep].z, xr[rep].w};
            #pragma unroll
            for (int u = 0; u < 4; u++)
                *(u64*)&xs[c4 + u][2 * r] = pack2(v[u], v[u]);
        }
        // load weight chunks (L2-hot after first wave)
        {
            const float* wptr = wq;
            #pragma unroll
            for (int w = 0; w < 3; w++) {
                wptr = (w == 0) ? wq : (w == 1) ? wk : wv;
                #pragma unroll
                for (int rep = 0; rep < 4; rep++) {
                    int idx = t + rep * 256;
                    int k = idx >> 4, h4 = (idx & 15) * 4;
                    *(float4*)&ws[w * 64 + k][h4] =
                        *(const float4*)&wptr[(size_t)(ch * 64 + k) * HDIM + h4];
                }
            }
        }
        __syncthreads();
        // prefetch next x chunk (overlaps the GEMM below)
        if (ch < 3) {
            #pragma unroll
            for (int rep = 0; rep < 4; rep++) {
                int idx = t + rep * 256;
                int r = idx >> 4, c4 = (idx & 15) * 4;
                xr[rep] = *(const float4*)&x[(size_t)(r0 + r) * CDIM + (ch + 1) * 64 + c4];
            }
        }
        // GEMM: 24 FFMA2 per k
        #pragma unroll 8
        for (int k = 0; k < 64; k++) {
            ulonglong2 a01 = *(const ulonglong2*)&xs[k][tr * 8];
            ulonglong2 a23 = *(const ulonglong2*)&xs[k][tr * 8 + 4];
            u64 av[4] = {a01.x, a01.y, a23.x, a23.y};
            #pragma unroll
            for (int w = 0; w < 3; w++) {
                ulonglong2 b = *(const ulonglong2*)&ws[w * 64 + k][tc * 4];
                u64 bv[2] = {b.x, b.y};
                #pragma unroll
                for (int i = 0; i < 4; i++)
                    #pragma unroll
                    for (int j = 0; j < 2; j++)
                        acc[w][i][j] = fma2(av[i], bv[j], acc[w][i][j]);
            }
        }
    }

    // epilogue
    #pragma unroll
    for (int w = 0; w < 3; w++) {
        float* optr = (w == 0) ? g_q : (w == 1) ? g_k : g_v;
        #pragma unroll
        for (int i = 0; i < 4; i++) {
            float c0, c1, c2, c3;
            unpack2(acc[w][i][0], c0, c1);
            unpack2(acc[w][i][1], c2, c3);
            *(float4*)&optr[(size_t)(r0 + tr * 4 + i) * HDIM + tc * 4] =
                make_float4(c0, c1, c2, c3);
        }
    }
}

// ---------------------------------------------------------------------------
// Kernel 2: causal flash attention on f32x2, register-prefetched K/V pipeline.
// Grid: (12, 32). Block 256. smem: qs_dup + ks + vs + ps_dup = 106496 B.
// ---------------------------------------------------------------------------
__global__ __launch_bounds__(256, 2) void attn_kernel(float* __restrict__ out)
{
    extern __shared__ float sm[];
    float (*qs)[DUP_STRIDE] = (float(*)[DUP_STRIDE])sm;                       // qs[h][2i] (scaled, dup)
    float (*ks)[B_STRIDE]   = (float(*)[B_STRIDE])(sm + 64 * DUP_STRIDE);     // ks[h][j]  (K^T)
    float (*vs)[B_STRIDE]   = (float(*)[B_STRIDE])(sm + 64 * DUP_STRIDE + 64 * B_STRIDE); // vs[j][h]
    float (*ps)[DUP_STRIDE] = (float(*)[DUP_STRIDE])(sm + 64 * DUP_STRIDE + 2 * 64 * B_STRIDE); // ps[j][2i] (dup)

    const int qi = blockIdx.x;
    const int b  = blockIdx.y;
    const int q0 = qi * 64;
    const int t  = threadIdx.x;
    const int tr = t >> 4;
    const int tc = t & 15;
    const float scale = 0.125f;   // 1/sqrt(64), folded into Q

    // load Q tile: transposed, scaled, duplicated
    #pragma unroll
    for (int rep = 0; rep < 4; rep++) {
        int idx = t + rep * 256;
        int r = idx >> 4, h4 = (idx & 15) * 4;
        float4 qv = *(const float4*)&g_q[(size_t)(b * SEQ + q0 + r) * HDIM + h4];
        float v[4] = {qv.x * scale, qv.y * scale, qv.z * scale, qv.w * scale};
        #pragma unroll
        for (int u = 0; u < 4; u++)
            *(u64*)&qs[h4 + u][2 * r] = pack2(v[u], v[u]);
    }

    // prefetch K/V tile 0 into registers
    float4 kr[4], vr[4];
    {
        const size_t kbase = (size_t)(b * SEQ) * HDIM;
        #pragma unroll
        for (int rep = 0; rep < 4; rep++) {
            int idx = t + rep * 256;
            int j = idx >> 4, h4 = (idx & 15) * 4;
            kr[rep] = *(const float4*)&g_k[kbase + (size_t)j * HDIM + h4];
            vr[rep] = *(const float4*)&g_v[kbase + (size_t)j * HDIM + h4];
        }
    }

    u64 o2[4][2];
    #pragma unroll
    for (int i = 0; i < 4; i++) { o2[i][0] = 0ull; o2[i][1] = 0ull; }
    float m[4], l[4];
    #pragma unroll
    for (int i = 0; i < 4; i++) { m[i] = -1e30f; l[i] = 0.0f; }

    for (int kt = 0; kt <= qi; kt++) {
        __syncthreads();   // prev PV done with vs/ps; first iter: qs writes done

        // commit prefetched K (transposed) and V (natural)
        #pragma unroll
        for (int rep = 0; rep < 4; rep++) {
            int idx = t + rep * 256;
            int j = idx >> 4, h4 = (idx & 15) * 4;
            float kv[4] = {kr[rep].x, kr[rep].y, kr[rep].z, kr[rep].w};
            #pragma unroll
            for (int u = 0; u < 4; u++) ks[h4 + u][j] = kv[u];
            *(float4*)&vs[j][h4] = vr[rep];
        }
        __syncthreads();

        // prefetch next tile (overlaps S GEMM + softmax + PV)
        if (kt < qi) {
            const size_t nbase = (size_t)(b * SEQ + (kt + 1) * 64) * HDIM;
            #pragma unroll
            for (int rep = 0; rep < 4; rep++) {
                int idx = t + rep * 256;
                int j = idx >> 4, h4 = (idx & 15) * 4;
                kr[rep] = *(const float4*)&g_k[nbase + (size_t)j * HDIM + h4];
                vr[rep] = *(const float4*)&g_v[nbase + (size_t)j * HDIM + h4];
            }
        }

        // S = (Q*scale) K^T  -- 8 FFMA2 per h
        u64 s2[4][2];
        #pragma unroll
        for (int i = 0; i < 4; i++) { s2[i][0] = 0ull; s2[i][1] = 0ull; }
        #pragma unroll 8
        for (int h = 0; h < 64; h++) {
            ulonglong2 a01 = *(const ulonglong2*)&qs[h][tr * 8];
            ulonglong2 a23 = *(const ulonglong2*)&qs[h][tr * 8 + 4];
            u64 av[4] = {a01.x, a01.y, a23.x, a23.y};
            ulonglong2 bb = *(const ulonglong2*)&ks[h][tc * 4];
            u64 bv[2] = {bb.x, bb.y};
            #pragma unroll
            for (int i = 0; i < 4; i++)
                #pragma unroll
                for (int j = 0; j < 2; j++)
                    s2[i][j] = fma2(av[i], bv[j], s2[i][j]);
        }

        // unpack scores
        float s[4][4];
        #pragma unroll
        for (int i = 0; i < 4; i++) {
            unpack2(s2[i][0], s[i][0], s[i][1]);
            unpack2(s2[i][1], s[i][2], s[i][3]);
        }

        // causal mask (diagonal tile only)
        if (kt == qi) {
            #pragma unroll
            for (int i = 0; i < 4; i++)
                #pragma unroll
                for (int j = 0; j < 4; j++)
                    if ((tc * 4 + j) > (tr * 4 + i)) s[i][j] = -1e30f;
        }

        // row max across the 16 tc-lanes
        float mt[4];
        #pragma unroll
        for (int i = 0; i < 4; i++)
            mt[i] = fmaxf(fmaxf(s[i][0], s[i][1]), fmaxf(s[i][2], s[i][3]));
        #pragma unroll
        for (int off = 1; off < 16; off <<= 1)
            #pragma unroll
            for (int i = 0; i < 4; i++)
                mt[i] = fmaxf(mt[i], __shfl_xor_sync(0xffffffffu, mt[i], off));

        float esc[4];
        #pragma unroll
        for (int i = 0; i < 4; i++) {
            float mn = fmaxf(m[i], mt[i]);
            esc[i] = __expf(m[i] - mn);
            m[i] = mn;
        }

        // p = exp(s - m) in place; row sums
        float rs[4] = {0.f, 0.f, 0.f, 0.f};
        #pragma unroll
        for (int i = 0; i < 4; i++)
            #pragma unroll
            for (int j = 0; j < 4; j++) {
                float pv = __expf(s[i][j] - m[i]);
                s[i][j] = pv;
                rs[i] += pv;
            }
        #pragma unroll
        for (int off = 1; off < 16; off <<= 1)
            #pragma unroll
            for (int i = 0; i < 4; i++)
                rs[i] += __shfl_xor_sync(0xffffffffu, rs[i], off);

        #pragma unroll
        for (int i = 0; i < 4; i++) {
            l[i] = l[i] * esc[i] + rs[i];
            u64 e2 = pack2(esc[i], esc[i]);
            o2[i][0] = mul2(o2[i][0], e2);
            o2[i][1] = mul2(o2[i][1], e2);
        }

        // stage P transposed + duplicated
        #pragma unroll
        for (int i = 0; i < 4; i++)
            #pragma unroll
            for (int j = 0; j < 4; j++)
                *(u64*)&ps[tc * 4 + j][2 * (tr * 4 + i)] = pack2(s[i][j], s[i][j]);
        __syncthreads();

        // O += P V  -- 8 FFMA2 per j
        #pragma unroll 8
        for (int j = 0; j < 64; j++) {
            ulonglong2 a01 = *(const ulonglong2*)&ps[j][tr * 8];
            ulonglong2 a23 = *(const ulonglong2*)&ps[j][tr * 8 + 4];
            u64 av[4] = {a01.x, a01.y, a23.x, a23.y};
            ulonglong2 bb = *(const ulonglong2*)&vs[j][tc * 4];
            u64 bv[2] = {bb.x, bb.y};
            #pragma unroll
            for (int i = 0; i < 4; i++)
                #pragma unroll
                for (int c = 0; c < 2; c++)
                    o2[i][c] = fma2(av[i], bv[c], o2[i][c]);
        }
    }

    // normalize + write
    #pragma unroll
    for (int i = 0; i < 4; i++) {
        float inv = 1.0f / l[i];
        float c0, c1, c2, c3;
        unpack2(o2[i][0], c0, c1);
        unpack2(o2[i][1], c2, c3);
        *(float4*)&out[(size_t)(b * SEQ + q0 + tr * 4 + i) * HDIM + tc * 4] =
            make_float4(c0 * inv, c1 * inv, c2 * inv, c3 * inv);
    }
}

// ---------------------------------------------------------------------------
extern "C" void kernel_launch(void* const* d_in, const int* in_sizes, int n_in,
                              void* d_out, int out_size)
{
    const float* x  = (const float*)d_in[0];
    const float* wq = (const float*)d_in[1];
    const float* wk = (const float*)d_in[2];
    const float* wv = (const float*)d_in[3];
    float* out = (float*)d_out;

    const int QKV_SMEM  = (64 * DUP_STRIDE + 3 * 64 * B_STRIDE) * (int)sizeof(float);   // 88064
    const int ATTN_SMEM = (2 * 64 * DUP_STRIDE + 2 * 64 * B_STRIDE) * (int)sizeof(float); // 106496

    cudaFuncSetAttribute(qkv_kernel,  cudaFuncAttributeMaxDynamicSharedMemorySize, QKV_SMEM);
    cudaFuncSetAttribute(attn_kernel, cudaFuncAttributeMaxDynamicSharedMemorySize, ATTN_SMEM);

    qkv_kernel<<<ROWS / 64, 256, QKV_SMEM>>>(x, wq, wk, wv);
    attn_kernel<<<dim3(QTILES, BATCH), 256, ATTN_SMEM>>>(out);
}

// round 5
// speedup vs baseline: 3.2686x; 3.2686x over previous
#include <cuda_runtime.h>
#include <cuda_bf16.h>

typedef unsigned int u32;

#define BATCH 32
#define SEQ   768
#define CDIM  256
#define HDIM  64
#define ROWS  (BATCH * SEQ)   // 24576

// split-bf16 scratch: one row = 64 bf16 = 8 uint4
__device__ uint4 g_qhi[ROWS * 8];
__device__ uint4 g_qlo[ROWS * 8];
__device__ uint4 g_khi[ROWS * 8];
__device__ uint4 g_klo[ROWS * 8];
__device__ uint4 g_vhi[ROWS * 8];
__device__ uint4 g_vlo[ROWS * 8];

// ---------------------------------------------------------------- helpers
__device__ __forceinline__ u32 smem_u32(const void* p) {
    u32 a; asm("{ .reg .u64 t; cvta.to.shared.u64 t, %1; cvt.u32.u64 %0, t; }" : "=r"(a) : "l"(p));
    return a;
}
// smem tile layout: [row][64 bf16] = 128B rows, 8 x 16B chunks, chunk swizzled by row
__device__ __forceinline__ u32 swz_addr(u32 base, int row, int chunk) {
    return base + (row << 7) + (((chunk ^ (row & 7))) << 4);
}
// A-fragment / trans-B-fragment address pattern (16x16 region at (m0,k0))
__device__ __forceinline__ u32 addr_A(u32 base, int lane, int m0, int k0) {
    int row = m0 + (lane & 15);
    int ch  = (k0 >> 3) + (lane >> 4);
    return swz_addr(base, row, ch);
}
// non-trans B-fragment (K-style, two n8 x one k16 at (n0,k0), X stored [n][k])
__device__ __forceinline__ u32 addr_B(u32 base, int lane, int n0, int k0) {
    int row = n0 + (lane & 7) + ((lane >> 4) << 3);
    int ch  = (k0 >> 3) + ((lane >> 3) & 1);
    return swz_addr(base, row, ch);
}
__device__ __forceinline__ void ldm4(u32* r, u32 a) {
    asm volatile("ldmatrix.sync.aligned.m8n8.x4.shared.b16 {%0,%1,%2,%3}, [%4];"
                 : "=r"(r[0]), "=r"(r[1]), "=r"(r[2]), "=r"(r[3]) : "r"(a));
}
__device__ __forceinline__ void ldm4t(u32* r, u32 a) {
    asm volatile("ldmatrix.sync.aligned.m8n8.x4.trans.shared.b16 {%0,%1,%2,%3}, [%4];"
                 : "=r"(r[0]), "=r"(r[1]), "=r"(r[2]), "=r"(r[3]) : "r"(a));
}
__device__ __forceinline__ void mma_bf(float* c, const u32* a, const u32* b) {
    asm volatile("mma.sync.aligned.m16n8k16.row.col.f32.bf16.bf16.f32 "
                 "{%0,%1,%2,%3},{%4,%5,%6,%7},{%8,%9},{%0,%1,%2,%3};"
                 : "+f"(c[0]), "+f"(c[1]), "+f"(c[2]), "+f"(c[3])
                 : "r"(a[0]), "r"(a[1]), "r"(a[2]), "r"(a[3]), "r"(b[0]), "r"(b[1]));
}
__device__ __forceinline__ void cp16(u32 d, const void* s) {
    asm volatile("cp.async.cg.shared.global [%0], [%1], 16;" :: "r"(d), "l"(s));
}
#define CP_COMMIT() asm volatile("cp.async.commit_group;" ::: "memory")
#define CP_WAIT1()  asm volatile("cp.async.wait_group 1;" ::: "memory")
#define CP_WAIT0()  asm volatile("cp.async.wait_group 0;" ::: "memory")

__device__ __forceinline__ u32 pk(float a, float b) {
    __nv_bfloat162 r = __floats2bfloat162_rn(a, b);
    return *reinterpret_cast<u32*>(&r);
}
__device__ __forceinline__ float bf_hi(float f) {
    return __bfloat162float(__float2bfloat16_rn(f));
}
__device__ __forceinline__ float ex2(float x) {
    float r; asm("ex2.approx.f32 %0, %1;" : "=f"(r) : "f"(x)); return r;
}

// ---------------------------------------------------------------- kernel 1
// QKV projection. Grid (192, 3); CTA: 128 rows x 64 cols, K chunked by 64.
#define XHI 0
#define XLO 16384
#define WHI 32768
#define WLO 40960
#define QKV_SMEM 49152

__global__ __launch_bounds__(256, 1) void qkv_kernel(
    const float* __restrict__ x, const float* __restrict__ wq,
    const float* __restrict__ wk, const float* __restrict__ wv)
{
    extern __shared__ char smc[];
    const u32 sb = smem_u32(smc);
    const int t = threadIdx.x, lane = t & 31, wid = t >> 5;
    const int wm = wid & 3, wn = wid >> 2;
    const int r0 = blockIdx.x * 128;
    const int which = blockIdx.y;
    const float* __restrict__ w = (which == 0) ? wq : (which == 1) ? wk : wv;

    float acc[2][4][4];
    #pragma unroll
    for (int i = 0; i < 2; i++)
        #pragma unroll
        for (int j = 0; j < 4; j++)
            #pragma unroll
            for (int k = 0; k < 4; k++) acc[i][j][k] = 0.f;

    // register prefetch chunk 0
    float4 xr[4][2]; float4 wr[2][2];
    #pragma unroll
    for (int rep = 0; rep < 4; rep++) {
        int idx = t + rep * 256, r = idx >> 3, c = idx & 7;
        xr[rep][0] = *(const float4*)&x[(size_t)(r0 + r) * CDIM + c * 8];
        xr[rep][1] = *(const float4*)&x[(size_t)(r0 + r) * CDIM + c * 8 + 4];
    }
    #pragma unroll
    for (int rep = 0; rep < 2; rep++) {
        int idx = t + rep * 256, r = idx >> 3, c = idx & 7;
        wr[rep][0] = *(const float4*)&w[(size_t)r * HDIM + c * 8];
        wr[rep][1] = *(const float4*)&w[(size_t)r * HDIM + c * 8 + 4];
    }

    for (int ch = 0; ch < 4; ch++) {
        __syncthreads();
        // commit x chunk (split hi/lo, swizzled)
        #pragma unroll
        for (int rep = 0; rep < 4; rep++) {
            int idx = t + rep * 256, r = idx >> 3, c = idx & 7;
            float f[8] = {xr[rep][0].x, xr[rep][0].y, xr[rep][0].z, xr[rep][0].w,
                          xr[rep][1].x, xr[rep][1].y, xr[rep][1].z, xr[rep][1].w};
            u32 hi[4], lo[4];
            #pragma unroll
            for (int u = 0; u < 4; u++) {
                float h0 = bf_hi(f[2 * u]), h1 = bf_hi(f[2 * u + 1]);
                hi[u] = pk(h0, h1);
                lo[u] = pk(f[2 * u] - h0, f[2 * u + 1] - h1);
            }
            u32 off = (u32)(r << 7) + (u32)((c ^ (r & 7)) << 4);
            *(uint4*)(smc + XHI + off) = make_uint4(hi[0], hi[1], hi[2], hi[3]);
            *(uint4*)(smc + XLO + off) = make_uint4(lo[0], lo[1], lo[2], lo[3]);
        }
        // commit w chunk
        #pragma unroll
        for (int rep = 0; rep < 2; rep++) {
            int idx = t + rep * 256, r = idx >> 3, c = idx & 7;
            float f[8] = {wr[rep][0].x, wr[rep][0].y, wr[rep][0].z, wr[rep][0].w,
                          wr[rep][1].x, wr[rep][1].y, wr[rep][1].z, wr[rep][1].w};
            u32 hi[4], lo[4];
            #pragma unroll
            for (int u = 0; u < 4; u++) {
                float h0 = bf_hi(f[2 * u]), h1 = bf_hi(f[2 * u + 1]);
                hi[u] = pk(h0, h1);
                lo[u] = pk(f[2 * u] - h0, f[2 * u + 1] - h1);
            }
            u32 off = (u32)(r << 7) + (u32)((c ^ (r & 7)) << 4);
            *(uint4*)(smc + WHI + off) = make_uint4(hi[0], hi[1], hi[2], hi[3]);
            *(uint4*)(smc + WLO + off) = make_uint4(lo[0], lo[1], lo[2], lo[3]);
        }
        __syncthreads();
        // prefetch next chunk (overlaps MMAs below)
        if (ch < 3) {
            #pragma unroll
            for (int rep = 0; rep < 4; rep++) {
                int idx = t + rep * 256, r = idx >> 3, c = idx & 7;
                xr[rep][0] = *(const float4*)&x[(size_t)(r0 + r) * CDIM + (ch + 1) * 64 + c * 8];
                xr[rep][1] = *(const float4*)&x[(size_t)(r0 + r) * CDIM + (ch + 1) * 64 + c * 8 + 4];
            }
            #pragma unroll
            for (int rep = 0; rep < 2; rep++) {
                int idx = t + rep * 256, r = idx >> 3, c = idx & 7;
                wr[rep][0] = *(const float4*)&w[(size_t)((ch + 1) * 64 + r) * HDIM + c * 8];
                wr[rep][1] = *(const float4*)&w[(size_t)((ch + 1) * 64 + r) * HDIM + c * 8 + 4];
            }
        }
        // MMAs: 96 per warp per chunk
        #pragma unroll
        for (int k16 = 0; k16 < 4; k16++) {
            int k0 = k16 * 16;
            u32 ah[2][4], al[2][4];
            #pragma unroll
            for (int ms = 0; ms < 2; ms++) {
                ldm4(ah[ms], addr_A(sb + XHI, lane, wm * 32 + ms * 16, k0));
                ldm4(al[ms], addr_A(sb + XLO, lane, wm * 32 + ms * 16, k0));
            }
            #pragma unroll
            for (int np = 0; np < 2; np++) {
                u32 bh[4], bl[4];
                ldm4t(bh, addr_A(sb + WHI, lane, k0, wn * 32 + np * 16));
                ldm4t(bl, addr_A(sb + WLO, lane, k0, wn * 32 + np * 16));
                #pragma unroll
                for (int ms = 0; ms < 2; ms++) {
                    mma_bf(acc[ms][np * 2],     ah[ms], bh);
                    mma_bf(acc[ms][np * 2 + 1], ah[ms], bh + 2);
                    mma_bf(acc[ms][np * 2],     ah[ms], bl);
                    mma_bf(acc[ms][np * 2 + 1], ah[ms], bl + 2);
                    mma_bf(acc[ms][np * 2],     al[ms], bh);
                    mma_bf(acc[ms][np * 2 + 1], al[ms], bh + 2);
                }
            }
        }
    }

    // epilogue: Q gets 0.125 * log2(e) folded in; split to bf16 hi/lo scratch
    const float scale = (which == 0) ? 0.18033688f : 1.0f;
    u32* dh = (u32*)((which == 0) ? g_qhi : (which == 1) ? g_khi : g_vhi);
    u32* dl = (u32*)((which == 0) ? g_qlo : (which == 1) ? g_klo : g_vlo);
    const int g = lane >> 2, tt = (lane & 3) * 2;
    #pragma unroll
    for (int ms = 0; ms < 2; ms++)
        #pragma unroll
        for (int f = 0; f < 4; f++)
            #pragma unroll
            for (int gg = 0; gg < 2; gg++) {
                int row = r0 + wm * 32 + ms * 16 + g + gg * 8;
                int col = wn * 32 + f * 8 + tt;
                float v0 = acc[ms][f][gg * 2] * scale;
                float v1 = acc[ms][f][gg * 2 + 1] * scale;
                float h0 = bf_hi(v0), h1 = bf_hi(v1);
                dh[row * 32 + (col >> 1)] = pk(h0, h1);
                dl[row * 32 + (col >> 1)] = pk(v0 - h0, v1 - h1);
            }
}

// ---------------------------------------------------------------- kernel 2
// Flash attention. Grid 192; CTA = (batch, 128-row q tile); 8 warps x 16 rows.
#define AQH 0
#define AQL 16384
#define AKV 32768
#define STG 65536          // per stage: KH +0, KL +16K, VH +32K, VL +48K
#define A_SMEM (AKV + 2 * STG)  // 163840

__global__ __launch_bounds__(256, 1) void attn_kernel(float* __restrict__ out)
{
    extern __shared__ char smc[];
    const u32 sb = smem_u32(smc);
    const int t = threadIdx.x, lane = t & 31, wid = t >> 5;
    const int m0 = wid * 16;
    const int qi = 5 - (int)(blockIdx.x >> 5);   // heavy tiles first
    const int b  = blockIdx.x & 31;
    const int q0 = qi * 128;
    const size_t tok0 = (size_t)b * SEQ;

    // prologue: Q + KV stage 0
    #pragma unroll
    for (int rep = 0; rep < 4; rep++) {
        int idx = t + rep * 256, r = idx >> 3, c = idx & 7;
        u32 off = (u32)(r << 7) + (u32)((c ^ (r & 7)) << 4);
        cp16(sb + AQH + off, &g_qhi[(tok0 + q0 + r) * 8 + c]);
        cp16(sb + AQL + off, &g_qlo[(tok0 + q0 + r) * 8 + c]);
        cp16(sb + AKV + 0     + off, &g_khi[(tok0 + r) * 8 + c]);
        cp16(sb + AKV + 16384 + off, &g_klo[(tok0 + r) * 8 + c]);
        cp16(sb + AKV + 32768 + off, &g_vhi[(tok0 + r) * 8 + c]);
        cp16(sb + AKV + 49152 + off, &g_vlo[(tok0 + r) * 8 + c]);
    }
    CP_COMMIT();

    float oacc[8][4];
    #pragma unroll
    for (int i = 0; i < 8; i++)
        #pragma unroll
        for (int j = 0; j < 4; j++) oacc[i][j] = 0.f;
    float ls0 = 0.f, ls1 = 0.f;
    const int g = lane >> 2, tt = (lane & 3) * 2;

    for (int kt = 0; kt <= qi; kt++) {
        const u32 cur = sb + AKV + (u32)(kt & 1) * STG;
        __syncthreads();                     // all warps done with other buffer
        if (kt < qi) {
            const u32 nxt = sb + AKV + (u32)((kt + 1) & 1) * STG;
            const size_t nb = tok0 + (size_t)(kt + 1) * 128;
            #pragma unroll
            for (int rep = 0; rep < 4; rep++) {
                int idx = t + rep * 256, r = idx >> 3, c = idx & 7;
                u32 off = (u32)(r << 7) + (u32)((c ^ (r & 7)) << 4);
                cp16(nxt + 0     + off, &g_khi[(nb + r) * 8 + c]);
                cp16(nxt + 16384 + off, &g_klo[(nb + r) * 8 + c]);
                cp16(nxt + 32768 + off, &g_vhi[(nb + r) * 8 + c]);
                cp16(nxt + 49152 + off, &g_vlo[(nb + r) * 8 + c]);
            }
            CP_COMMIT();
            CP_WAIT1();
        } else {
            CP_WAIT0();
        }
        __syncthreads();                     // current stage visible to all

        // ---- S = Q K^T (128x... this warp: 16 rows x 128 cols)
        float sacc[16][4];
        #pragma unroll
        for (int i = 0; i < 16; i++)
            #pragma unroll
            for (int j = 0; j < 4; j++) sacc[i][j] = 0.f;
        #pragma unroll
        for (int k16 = 0; k16 < 4; k16++) {
            int k0 = k16 * 16;
            u32 ah[4], al[4];
            ldm4(ah, addr_A(sb + AQH, lane, m0, k0));
            ldm4(al, addr_A(sb + AQL, lane, m0, k0));
            #pragma unroll
            for (int np = 0; np < 8; np++) {
                u32 bh[4], bl[4];
                ldm4(bh, addr_B(cur + 0,     lane, np * 16, k0));
                ldm4(bl, addr_B(cur + 16384, lane, np * 16, k0));
                mma_bf(sacc[np * 2],     ah, bh);
                mma_bf(sacc[np * 2 + 1], ah, bh + 2);
                mma_bf(sacc[np * 2],     ah, bl);
                mma_bf(sacc[np * 2 + 1], ah, bl + 2);
                mma_bf(sacc[np * 2],     al, bh);
                mma_bf(sacc[np * 2 + 1], al, bh + 2);
            }
        }

        // ---- softmax (no row max needed; scale*log2e pre-folded into Q)
        const bool diag = (kt == qi);
        const int rq0 = m0 + g;
        u32 ph[8][4], pl[8][4];
        #pragma unroll
        for (int f = 0; f < 16; f++) {
            int cb = f * 8 + tt;
            float p0 = ex2(sacc[f][0]), p1 = ex2(sacc[f][1]);
            float p2 = ex2(sacc[f][2]), p3 = ex2(sacc[f][3]);
            if (diag) {
                if (cb     > rq0)     p0 = 0.f;
                if (cb + 1 > rq0)     p1 = 0.f;
                if (cb     > rq0 + 8) p2 = 0.f;
                if (cb + 1 > rq0 + 8) p3 = 0.f;
            }
            ls0 += p0 + p1;
            ls1 += p2 + p3;
            float h0 = bf_hi(p0), h1 = bf_hi(p1), h2 = bf_hi(p2), h3 = bf_hi(p3);
            int j = f >> 1, hv = (f & 1) * 2;
            ph[j][hv]     = pk(h0, h1);
            ph[j][hv + 1] = pk(h2, h3);
            pl[j][hv]     = pk(p0 - h0, p1 - h1);
            pl[j][hv + 1] = pk(p2 - h2, p3 - h3);
        }

        // ---- O += P V  (V natural layout, trans-ldmatrix for B frags)
        #pragma unroll
        for (int np = 0; np < 4; np++) {
            int n0 = np * 16;
            #pragma unroll
            for (int j = 0; j < 8; j++) {
                int k0 = j * 16;
                u32 bh[4], bl[4];
                ldm4t(bh, addr_A(cur + 32768, lane, k0, n0));
                ldm4t(bl, addr_A(cur + 49152, lane, k0, n0));
                mma_bf(oacc[np * 2],     ph[j], bh);
                mma_bf(oacc[np * 2 + 1], ph[j], bh + 2);
                mma_bf(oacc[np * 2],     ph[j], bl);
                mma_bf(oacc[np * 2 + 1], ph[j], bl + 2);
                mma_bf(oacc[np * 2],     pl[j], bh);
                mma_bf(oacc[np * 2 + 1], pl[j], bh + 2);
            }
        }
    }

    // ---- epilogue: finish row sums, normalize, write
    ls0 += __shfl_xor_sync(0xffffffffu, ls0, 1);
    ls0 += __shfl_xor_sync(0xffffffffu, ls0, 2);
    ls1 += __shfl_xor_sync(0xffffffffu, ls1, 1);
    ls1 += __shfl_xor_sync(0xffffffffu, ls1, 2);
    float inv0 = 1.0f / ls0, inv1 = 1.0f / ls1;
    int row = q0 + m0 + g;
    float* op0 = out + (tok0 + row) * HDIM;
    float* op1 = out + (tok0 + row + 8) * HDIM;
    #pragma unroll
    for (int f = 0; f < 8; f++) {
        int col = f * 8 + tt;
        *(float2*)(op0 + col) = make_float2(oacc[f][0] * inv0, oacc[f][1] * inv0);
        *(float2*)(op1 + col) = make_float2(oacc[f][2] * inv1, oacc[f][3] * inv1);
    }
}

// ---------------------------------------------------------------- launch
extern "C" void kernel_launch(void* const* d_in, const int* in_sizes, int n_in,
                              void* d_out, int out_size)
{
    const float* x  = (const float*)d_in[0];
    const float* wq = (const float*)d_in[1];
    const float* wk = (const float*)d_in[2];
    const float* wv = (const float*)d_in[3];
    float* out = (float*)d_out;

    cudaFuncSetAttribute(qkv_kernel,  cudaFuncAttributeMaxDynamicSharedMemorySize, QKV_SMEM);
    cudaFuncSetAttribute(attn_kernel, cudaFuncAttributeMaxDynamicSharedMemorySize, A_SMEM);

    qkv_kernel<<<dim3(ROWS / 128, 3), 256, QKV_SMEM>>>(x, wq, wk, wv);
    attn_kernel<<<192, 256, A_SMEM>>>(out);
}